// round 2
// baseline (speedup 1.0000x reference)
#include <cuda_runtime.h>
#include <math.h>

#define IW 256
#define IH 256
#define HW (IW*IH)
#define NB 2
#define NC 96

// ======================= 1. backwarp + mean |diff| =========================
__global__ void warp_diff_kernel(const float* __restrict__ A,
                                 const float* __restrict__ Bf,
                                 const float* __restrict__ bi_flow,
                                 int flow_ch, float* __restrict__ mout)
{
    int idx = blockIdx.x * blockDim.x + threadIdx.x;
    if (idx >= NB*HW) return;
    int b = idx / HW;
    int p = idx - b*HW;
    int y = p / IW, x = p - y*IW;

    const float* fl = bi_flow + (b*4 + flow_ch) * HW;
    float tx = (float)x + fl[p]      * 0.125f;
    float ty = (float)y + fl[HW + p] * 0.125f;
    float x0f = floorf(tx), y0f = floorf(ty);
    float fx = tx - x0f, fy = ty - y0f;
    int x0 = (int)x0f, y0 = (int)y0f;
    int x1 = x0 + 1,  y1 = y0 + 1;

    bool vx0 = (x0 >= 0) & (x0 < IW), vx1 = (x1 >= 0) & (x1 < IW);
    bool vy0 = (y0 >= 0) & (y0 < IH), vy1 = (y1 >= 0) & (y1 < IH);
    bool v00 = vx0 & vy0, v10 = vx1 & vy0, v01 = vx0 & vy1, v11 = vx1 & vy1;
    float w00 = (1.f-fx)*(1.f-fy), w10 = fx*(1.f-fy);
    float w01 = (1.f-fx)*fy,       w11 = fx*fy;
    int o00 = v00 ? (y0*IW + x0) : 0;
    int o10 = v10 ? (y0*IW + x1) : 0;
    int o01 = v01 ? (y1*IW + x0) : 0;
    int o11 = v11 ? (y1*IW + x1) : 0;

    const float* Ab = A  + b*NC*HW + p;
    const float* Bb = Bf + b*NC*HW;
    float acc = 0.f;
    #pragma unroll 4
    for (int c = 0; c < NC; ++c) {
        const float* Bc = Bb + c*HW;
        float wv = 0.f;
        if (v00) wv += w00 * Bc[o00];
        if (v10) wv += w10 * Bc[o10];
        if (v01) wv += w01 * Bc[o01];
        if (v11) wv += w11 * Bc[o11];
        acc += fabsf(Ab[c*HW] - wv);
    }
    mout[idx] = acc * (1.f/96.f);
}

// ======================= 2. convolutions ===================================
// conv (NIC in -> 64 out), 3x3 SAME, leaky 0.1.
// Block: 512 threads, 32x4 output tile, each thread: 4 out-ch x 4 rows.
template<int NIC, bool HASM>
__global__ __launch_bounds__(512)
void conv64_kernel(const float* __restrict__ mptr_base,  // [B,H,W] metric (or null)
                   const float* __restrict__ feat,       // NIC-1 (or NIC) channels
                   const float* __restrict__ wt,         // [64, NIC, 3, 3]
                   const float* __restrict__ bias,
                   float* __restrict__ out)              // [B,64,H,W]
{
    __shared__ float sp[6*34];
    __shared__ float sw[64*9];
    int tid = threadIdx.x;
    int x0 = blockIdx.x * 32;
    int y0 = blockIdx.y * 4;
    int b  = blockIdx.z;
    int xx = tid & 31;
    int g  = tid >> 5;          // 0..15
    int ocb = g * 4;

    const float* mptr = HASM ? (mptr_base + b*HW) : nullptr;

    float acc[4][4];
    #pragma unroll
    for (int j = 0; j < 4; ++j)
        #pragma unroll
        for (int r = 0; r < 4; ++r) acc[j][r] = 0.f;

    for (int ic = 0; ic < NIC; ++ic) {
        const float* src;
        if (HASM) src = (ic == 0) ? mptr : (feat + (b*(NIC-1) + (ic-1))*HW);
        else      src = feat + (b*NIC + ic)*HW;

        for (int i = tid; i < 6*34; i += 512) {
            int r = i / 34, c = i - r*34;
            int gy = y0 - 1 + r, gx = x0 - 1 + c;
            sp[i] = (gy >= 0 && gy < IH && gx >= 0 && gx < IW) ? src[gy*IW + gx] : 0.f;
        }
        for (int i = tid; i < 576; i += 512) {
            int oc = i / 9, k = i - oc*9;
            sw[i] = wt[(oc*NIC + ic)*9 + k];
        }
        __syncthreads();

        float wr[4][9];
        #pragma unroll
        for (int j = 0; j < 4; ++j)
            #pragma unroll
            for (int k = 0; k < 9; ++k) wr[j][k] = sw[(ocb + j)*9 + k];

        #pragma unroll
        for (int r = 0; r < 4; ++r) {
            float p[9];
            #pragma unroll
            for (int ky = 0; ky < 3; ++ky)
                #pragma unroll
                for (int kx = 0; kx < 3; ++kx)
                    p[ky*3 + kx] = sp[(r + ky)*34 + xx + kx];
            #pragma unroll
            for (int j = 0; j < 4; ++j)
                #pragma unroll
                for (int k = 0; k < 9; ++k)
                    acc[j][r] = fmaf(wr[j][k], p[k], acc[j][r]);
        }
        __syncthreads();
    }

    #pragma unroll
    for (int j = 0; j < 4; ++j) {
        int oc = ocb + j;
        float bv = bias[oc];
        #pragma unroll
        for (int r = 0; r < 4; ++r) {
            float v = acc[j][r] + bv;
            v = v > 0.f ? v : 0.1f * v;
            out[((b*64 + oc)*IH + y0 + r)*IW + x0 + xx] = v;
        }
    }
}

// conv3: 64 -> 1, then emet = exp(clip(alpha * (conv+b), -20, 20))
__global__ __launch_bounds__(256)
void conv3_kernel(const float* __restrict__ x,
                  const float* __restrict__ wt,   // [1,64,3,3]
                  const float* __restrict__ bias,
                  const float* __restrict__ alpha,
                  float* __restrict__ emet)       // [B,H,W]
{
    __shared__ float sp[10*34];
    __shared__ float sw[9];
    int tid = threadIdx.x;
    int x0 = blockIdx.x * 32;
    int y0 = blockIdx.y * 8;
    int b  = blockIdx.z;
    int xx = tid & 31, yy = tid >> 5;   // 0..7

    float acc = 0.f;
    for (int ic = 0; ic < 64; ++ic) {
        const float* src = x + (b*64 + ic)*HW;
        for (int i = tid; i < 10*34; i += 256) {
            int r = i / 34, c = i - r*34;
            int gy = y0 - 1 + r, gx = x0 - 1 + c;
            sp[i] = (gy >= 0 && gy < IH && gx >= 0 && gx < IW) ? src[gy*IW + gx] : 0.f;
        }
        if (tid < 9) sw[tid] = wt[ic*9 + tid];
        __syncthreads();
        #pragma unroll
        for (int ky = 0; ky < 3; ++ky)
            #pragma unroll
            for (int kx = 0; kx < 3; ++kx)
                acc = fmaf(sw[ky*3 + kx], sp[(yy + ky)*34 + xx + kx], acc);
        __syncthreads();
    }
    float v = acc + bias[0];
    v = alpha[0] * v;
    v = fminf(fmaxf(v, -20.f), 20.f);
    emet[b*HW + (y0 + yy)*IW + x0 + xx] = __expf(v);
}

// ======================= 3. softsplat ======================================
__global__ void zero_kernel(float* __restrict__ p, int n4)
{
    int idx = blockIdx.x * blockDim.x + threadIdx.x;
    if (idx < n4) reinterpret_cast<float4*>(p)[idx] = make_float4(0,0,0,0);
}

__global__ void splat_kernel(const float* __restrict__ feat,
                             const float* __restrict__ bi_flow,
                             int flow_ch,
                             const float* __restrict__ emet,  // [B,H,W]
                             float* __restrict__ num,         // [B,96,H,W]
                             float* __restrict__ den)         // [B,H,W]
{
    int idx = blockIdx.x * blockDim.x + threadIdx.x;
    if (idx >= NB*HW) return;
    int b = idx / HW;
    int p = idx - b*HW;
    int y = p / IW, x = p - y*IW;

    const float* fl = bi_flow + (b*4 + flow_ch)*HW;
    float tx = (float)x + fl[p]      * 0.125f;
    float ty = (float)y + fl[HW + p] * 0.125f;
    float x0f = floorf(tx), y0f = floorf(ty);
    float fx = tx - x0f, fy = ty - y0f;
    int x0 = (int)x0f, y0 = (int)y0f;
    int x1 = x0 + 1,  y1 = y0 + 1;
    bool vx0 = (x0 >= 0) & (x0 < IW), vx1 = (x1 >= 0) & (x1 < IW);
    bool vy0 = (y0 >= 0) & (y0 < IH), vy1 = (y1 >= 0) & (y1 < IH);
    bool v00 = vx0 & vy0, v10 = vx1 & vy0, v01 = vx0 & vy1, v11 = vx1 & vy1;
    float w00 = (1.f-fx)*(1.f-fy), w10 = fx*(1.f-fy);
    float w01 = (1.f-fx)*fy,       w11 = fx*fy;
    int t00 = y0*IW + x0, t10 = y0*IW + x1;
    int t01 = y1*IW + x0, t11 = y1*IW + x1;

    float m = emet[idx];

    const float* fb = feat + b*NC*HW + p;
    float* nb = num + b*NC*HW;
    for (int c = 0; c < NC; ++c) {
        float v = fb[c*HW] * m;
        float* chan = nb + c*HW;
        if (v00) atomicAdd(chan + t00, v*w00);
        if (v10) atomicAdd(chan + t10, v*w10);
        if (v01) atomicAdd(chan + t01, v*w01);
        if (v11) atomicAdd(chan + t11, v*w11);
    }
    float* db = den + b*HW;
    if (v00) atomicAdd(db + t00, m*w00);
    if (v10) atomicAdd(db + t10, m*w10);
    if (v01) atomicAdd(db + t01, m*w01);
    if (v11) atomicAdd(db + t11, m*w11);
}

// In-place: out = num/(den+eps), num aliases out.
__global__ void normalize_kernel(float* __restrict__ num,
                                 const float* __restrict__ den)
{
    int idx = blockIdx.x * blockDim.x + threadIdx.x;     // float4 index
    if (idx >= NB*NC*HW/4) return;
    int e = idx * 4;
    int b = e / (NC*HW);
    int p = e % HW;
    float4 n = reinterpret_cast<const float4*>(num)[idx];
    float4 d = *reinterpret_cast<const float4*>(den + b*HW + p);
    float4 o;
    o.x = n.x / (d.x + 1e-7f);
    o.y = n.y / (d.y + 1e-7f);
    o.z = n.z / (d.z + 1e-7f);
    o.w = n.w / (d.w + 1e-7f);
    reinterpret_cast<float4*>(num)[idx] = o;
}

// ======================= 4. correlation ====================================
__global__ __launch_bounds__(256, 1)
void corr_kernel(const float* __restrict__ wl,
                 const float* __restrict__ wr,
                 float* __restrict__ cost)
{
    __shared__ float sa[8*32];
    __shared__ float sb[16*40];
    int tid = threadIdx.x;
    int x0 = blockIdx.x * 32;
    int y0 = blockIdx.y * 8;
    int b  = blockIdx.z;
    int xx = tid & 31, yy = tid >> 5;   // 0..7

    float acc[81];
    #pragma unroll
    for (int d = 0; d < 81; ++d) acc[d] = 0.f;

    for (int c = 0; c < NC; ++c) {
        const float* lsrc = wl + (b*NC + c)*HW;
        const float* rsrc = wr + (b*NC + c)*HW;
        sa[tid] = lsrc[(y0 + yy)*IW + x0 + xx];
        for (int i = tid; i < 16*40; i += 256) {
            int r = i / 40, col = i - r*40;
            int gy = y0 - 4 + r, gx = x0 - 4 + col;
            sb[i] = (gy >= 0 && gy < IH && gx >= 0 && gx < IW) ? rsrc[gy*IW + gx] : 0.f;
        }
        __syncthreads();
        float a = sa[tid];
        #pragma unroll
        for (int dy = 0; dy < 9; ++dy)
            #pragma unroll
            for (int dx = 0; dx < 9; ++dx)
                acc[dy*9 + dx] = fmaf(a, sb[(yy + dy)*40 + xx + dx], acc[dy*9 + dx]);
        __syncthreads();
    }
    #pragma unroll
    for (int d = 0; d < 81; ++d) {
        float v = acc[d] * (1.f/96.f);
        v = v > 0.f ? v : 0.1f * v;
        cost[((b*81 + d)*IH + y0 + yy)*IW + x0 + xx] = v;
    }
}

// ======================= launch ============================================
extern "C" void kernel_launch(void* const* d_in, const int* in_sizes, int n_in,
                              void* d_out, int out_size)
{
    const float* bi_flow = (const float*)d_in[0];
    const float* fL      = (const float*)d_in[1];
    const float* fR      = (const float*)d_in[2];
    const float* alpha   = (const float*)d_in[3];
    const float* w1 = (const float*)d_in[4];
    const float* b1 = (const float*)d_in[5];
    const float* w2 = (const float*)d_in[6];
    const float* b2 = (const float*)d_in[7];
    const float* w3 = (const float*)d_in[8];
    const float* b3 = (const float*)d_in[9];

    float* out  = (float*)d_out;
    float* wL   = out;                       // 12,582,912 floats
    float* wR   = out + (size_t)NB*NC*HW;    // 12,582,912 floats
    float* cost = out + (size_t)2*NB*NC*HW;  // 10,616,832 floats

    // Scratch carved out of the cost region (all dead before corr_kernel runs):
    float* s_mL    = cost;                   // 131072
    float* s_mR    = cost + 131072;          // 131072
    float* s_emetL = cost + 262144;          // 131072
    float* s_emetR = cost + 393216;          // 131072
    float* s_denL  = cost + 524288;          // 131072
    float* s_denR  = cost + 655360;          // 131072
    // x1 scratch lives in the wL region, x2 scratch in the wR region
    float* s_x1 = wL;                        // 8,388,608 <= 12,582,912
    float* s_x2 = wR;

    const int NPIX = NB*HW;
    dim3 gridC(IW/32, IH/4, NB);             // conv64 kernels: 512 threads
    dim3 grid3(IW/32, IH/8, NB);             // conv3/corr: 256 threads

    // ---- metrics ----
    warp_diff_kernel<<<(NPIX+255)/256, 256>>>(fL, fR, bi_flow, 0, s_mL);
    warp_diff_kernel<<<(NPIX+255)/256, 256>>>(fR, fL, bi_flow, 2, s_mR);

    // ---- metric_net L ----
    conv64_kernel<97, true><<<gridC, 512>>>(s_mL, fL, w1, b1, s_x1);
    conv64_kernel<64, false><<<gridC, 512>>>(nullptr, s_x1, w2, b2, s_x2);
    conv3_kernel<<<grid3, 256>>>(s_x2, w3, b3, alpha, s_emetL);

    // ---- metric_net R ----
    conv64_kernel<97, true><<<gridC, 512>>>(s_mR, fR, w1, b1, s_x1);
    conv64_kernel<64, false><<<gridC, 512>>>(nullptr, s_x1, w2, b2, s_x2);
    conv3_kernel<<<grid3, 256>>>(s_x2, w3, b3, alpha, s_emetR);

    // ---- softsplat L (num in wL region, in-place normalize) ----
    zero_kernel<<<(NB*NC*HW/4 + 255)/256, 256>>>(wL, NB*NC*HW/4);
    zero_kernel<<<(NPIX/4 + 255)/256, 256>>>(s_denL, NPIX/4);
    splat_kernel<<<(NPIX+255)/256, 256>>>(fL, bi_flow, 0, s_emetL, wL, s_denL);
    normalize_kernel<<<(NB*NC*HW/4 + 255)/256, 256>>>(wL, s_denL);

    // ---- softsplat R ----
    zero_kernel<<<(NB*NC*HW/4 + 255)/256, 256>>>(wR, NB*NC*HW/4);
    zero_kernel<<<(NPIX/4 + 255)/256, 256>>>(s_denR, NPIX/4);
    splat_kernel<<<(NPIX+255)/256, 256>>>(fR, bi_flow, 2, s_emetR, wR, s_denR);
    normalize_kernel<<<(NB*NC*HW/4 + 255)/256, 256>>>(wR, s_denR);

    // ---- correlation (overwrites all cost-region scratch) ----
    corr_kernel<<<grid3, 256>>>(wL, wR, cost);
}

// round 4
// speedup vs baseline: 1.5195x; 1.5195x over previous
#include <cuda_runtime.h>
#include <cuda.h>
#include <math.h>
#include <stdint.h>

#define IW 256
#define IH 256
#define HW (IW*IH)
#define NB 2
#define NC 96

__device__ __forceinline__ uint32_t f2tf32(float f){
    uint32_t r; asm("cvt.rna.tf32.f32 %0, %1;" : "=r"(r) : "f"(f)); return r;
}

// =============== tf32 mma.sync conv: NIC -> 64, 3x3 SAME, leaky 0.1 =========
// CTA tile: M=128 px (one row segment), N=64 oc, K=NIC*9 in 32-chunks.
// 8 warps: 4 along M (m32) x 2 along N (n32). Each warp: 2 m16-atoms x 4 n8-atoms.
#define AS_STRIDE 36
#define A_BUF (128*AS_STRIDE)     // floats
#define B_BUF (64*AS_STRIDE)

template<int NIC, bool HASM>
__global__ __launch_bounds__(256, 2)
void conv_mma_kernel(const float* __restrict__ metric,   // [B,H,W] or null
                     const float* __restrict__ feat,     // NIC-1 (or NIC) channels
                     const float* __restrict__ wt,       // [64, NIC, 3, 3]
                     const float* __restrict__ bias,
                     float* __restrict__ out)            // [B,64,H,W]
{
    extern __shared__ float sm[];
    float* As = sm;                    // [2][A_BUF]
    float* Bs = sm + 2*A_BUF;          // [2][B_BUF]
    __shared__ float sbias[64];

    constexpr int KTOT = NIC*9;
    constexpr int NCH  = (KTOT + 31)/32;   // 28 (conv1) / 18 (conv2)

    const int tid  = threadIdx.x;
    const int lane = tid & 31;
    const int warp = tid >> 5;
    const int wm = (warp >> 1) * 32;       // warp M offset
    const int wn = (warp & 1) * 32;        // warp N offset

    // tile: 128 consecutive x in one image row
    const int t  = blockIdx.x;
    const int b  = t >> 9;
    const int r  = t & 511;
    const int y0c = r >> 1;
    const int x0c = (r & 1) << 7;

    if (tid < 64) sbias[tid] = bias[tid];

    float acc[2][4][4];
    #pragma unroll
    for (int i = 0; i < 2; ++i)
        #pragma unroll
        for (int j = 0; j < 4; ++j)
            #pragma unroll
            for (int k = 0; k < 4; ++k) acc[i][j][k] = 0.f;

    // ---- prefetch helpers ----
    float areg[16], breg[8];

    auto load_chunk = [&](int ch) {
        // A: 128 px x 32 k  (im2col on the fly)
        #pragma unroll
        for (int i = 0; i < 16; ++i) {
            int e    = tid + i*256;
            int m    = e >> 5;
            int kk32 = e & 31;
            int kk   = ch*32 + kk32;
            int ic   = kk / 9;
            int tap  = kk - ic*9;
            int ty   = tap / 3;
            int tx   = tap - ty*3;
            int x = x0c + m + tx - 1;
            int y = y0c + ty - 1;
            float v = 0.f;
            if (ic < NIC && (unsigned)x < IW && (unsigned)y < IH) {
                const float* src;
                if (HASM) src = (ic == 0) ? (metric + (size_t)b*HW)
                                          : (feat + ((size_t)b*(NIC-1) + (ic-1))*HW);
                else      src = feat + ((size_t)b*NIC + ic)*HW;
                v = __ldg(src + y*IW + x);
            }
            areg[i] = v;
        }
        // B: 64 oc x 32 k
        #pragma unroll
        for (int i = 0; i < 8; ++i) {
            int e    = tid + i*256;
            int oc   = e >> 5;
            int kk32 = e & 31;
            int kk   = ch*32 + kk32;
            breg[i] = (kk < KTOT) ? __ldg(wt + (size_t)oc*KTOT + kk) : 0.f;
        }
    };
    auto store_chunk = [&](int buf) {
        float* ab = As + buf*A_BUF;
        float* bb = Bs + buf*B_BUF;
        #pragma unroll
        for (int i = 0; i < 16; ++i) {
            int e = tid + i*256;
            int m = e >> 5, kk32 = e & 31;
            ab[m*AS_STRIDE + kk32] = __uint_as_float(f2tf32(areg[i]));
        }
        #pragma unroll
        for (int i = 0; i < 8; ++i) {
            int e = tid + i*256;
            int oc = e >> 5, kk32 = e & 31;
            bb[oc*AS_STRIDE + kk32] = __uint_as_float(f2tf32(breg[i]));
        }
    };

    load_chunk(0);

    for (int s = 0; s < NCH; ++s) {
        const int buf = s & 1;
        store_chunk(buf);
        __syncthreads();
        if (s + 1 < NCH) load_chunk(s + 1);

        const float* ab = As + buf*A_BUF;
        const float* bb = Bs + buf*B_BUF;
        const int qr = lane >> 2;      // 0..7
        const int qc = lane & 3;       // 0..3

        #pragma unroll
        for (int k8 = 0; k8 < 4; ++k8) {
            const int k0 = k8*8;
            // A fragments: 2 m16 atoms
            uint32_t afr[2][4];
            #pragma unroll
            for (int am = 0; am < 2; ++am) {
                const float* base = ab + (wm + am*16 + qr)*AS_STRIDE + k0 + qc;
                afr[am][0] = __float_as_uint(base[0]);
                afr[am][1] = __float_as_uint(base[8*AS_STRIDE]);
                afr[am][2] = __float_as_uint(base[4]);
                afr[am][3] = __float_as_uint(base[8*AS_STRIDE + 4]);
            }
            // B fragments: 4 n8 atoms
            uint32_t bfr[4][2];
            #pragma unroll
            for (int j = 0; j < 4; ++j) {
                const float* base = bb + (wn + j*8 + qr)*AS_STRIDE + k0 + qc;
                bfr[j][0] = __float_as_uint(base[0]);
                bfr[j][1] = __float_as_uint(base[4]);
            }
            #pragma unroll
            for (int am = 0; am < 2; ++am)
                #pragma unroll
                for (int j = 0; j < 4; ++j)
                    asm volatile(
                        "mma.sync.aligned.m16n8k8.row.col.f32.tf32.tf32.f32 "
                        "{%0,%1,%2,%3}, {%4,%5,%6,%7}, {%8,%9}, {%0,%1,%2,%3};"
                        : "+f"(acc[am][j][0]), "+f"(acc[am][j][1]),
                          "+f"(acc[am][j][2]), "+f"(acc[am][j][3])
                        : "r"(afr[am][0]), "r"(afr[am][1]), "r"(afr[am][2]), "r"(afr[am][3]),
                          "r"(bfr[j][0]), "r"(bfr[j][1]));
        }
        __syncthreads();
    }

    // ---- epilogue: bias + leaky + store ----
    const int qr = lane >> 2;
    const int qc = lane & 3;
    #pragma unroll
    for (int am = 0; am < 2; ++am) {
        #pragma unroll
        for (int j = 0; j < 4; ++j) {
            #pragma unroll
            for (int h = 0; h < 2; ++h) {       // h: c0/c1 vs c2/c3 (row / row+8)
                int m  = wm + am*16 + qr + h*8;
                #pragma unroll
                for (int cc = 0; cc < 2; ++cc) {
                    int oc = wn + j*8 + qc*2 + cc;
                    float v = acc[am][j][h*2 + cc] + sbias[oc];
                    v = v > 0.f ? v : 0.1f * v;
                    out[(((size_t)b*64 + oc)*IH + y0c)*IW + x0c + m] = v;
                }
            }
        }
    }
}

// ======================= 1. backwarp + mean |diff| =========================
__global__ void warp_diff_kernel(const float* __restrict__ A,
                                 const float* __restrict__ Bf,
                                 const float* __restrict__ bi_flow,
                                 int flow_ch, float* __restrict__ mout)
{
    int idx = blockIdx.x * blockDim.x + threadIdx.x;
    if (idx >= NB*HW) return;
    int b = idx / HW;
    int p = idx - b*HW;
    int y = p / IW, x = p - y*IW;

    const float* fl = bi_flow + (b*4 + flow_ch) * HW;
    float tx = (float)x + fl[p]      * 0.125f;
    float ty = (float)y + fl[HW + p] * 0.125f;
    float x0f = floorf(tx), y0f = floorf(ty);
    float fx = tx - x0f, fy = ty - y0f;
    int x0 = (int)x0f, y0 = (int)y0f;
    int x1 = x0 + 1,  y1 = y0 + 1;

    bool vx0 = (x0 >= 0) & (x0 < IW), vx1 = (x1 >= 0) & (x1 < IW);
    bool vy0 = (y0 >= 0) & (y0 < IH), vy1 = (y1 >= 0) & (y1 < IH);
    bool v00 = vx0 & vy0, v10 = vx1 & vy0, v01 = vx0 & vy1, v11 = vx1 & vy1;
    float w00 = (1.f-fx)*(1.f-fy), w10 = fx*(1.f-fy);
    float w01 = (1.f-fx)*fy,       w11 = fx*fy;
    int o00 = v00 ? (y0*IW + x0) : 0;
    int o10 = v10 ? (y0*IW + x1) : 0;
    int o01 = v01 ? (y1*IW + x0) : 0;
    int o11 = v11 ? (y1*IW + x1) : 0;

    const float* Ab = A  + b*NC*HW + p;
    const float* Bb = Bf + b*NC*HW;
    float acc = 0.f;
    #pragma unroll 4
    for (int c = 0; c < NC; ++c) {
        const float* Bc = Bb + c*HW;
        float wv = 0.f;
        if (v00) wv += w00 * Bc[o00];
        if (v10) wv += w10 * Bc[o10];
        if (v01) wv += w01 * Bc[o01];
        if (v11) wv += w11 * Bc[o11];
        acc += fabsf(Ab[c*HW] - wv);
    }
    mout[idx] = acc * (1.f/96.f);
}

// conv3: 64 -> 1, then emet = exp(clip(alpha * (conv+b), -20, 20))
__global__ __launch_bounds__(256)
void conv3_kernel(const float* __restrict__ x,
                  const float* __restrict__ wt,   // [1,64,3,3]
                  const float* __restrict__ bias,
                  const float* __restrict__ alpha,
                  float* __restrict__ emet)       // [B,H,W]
{
    __shared__ float sp[10*34];
    __shared__ float sw[9];
    int tid = threadIdx.x;
    int x0 = blockIdx.x * 32;
    int y0 = blockIdx.y * 8;
    int b  = blockIdx.z;
    int xx = tid & 31, yy = tid >> 5;   // 0..7

    float acc = 0.f;
    for (int ic = 0; ic < 64; ++ic) {
        const float* src = x + (b*64 + ic)*HW;
        for (int i = tid; i < 10*34; i += 256) {
            int r = i / 34, c = i - r*34;
            int gy = y0 - 1 + r, gx = x0 - 1 + c;
            sp[i] = (gy >= 0 && gy < IH && gx >= 0 && gx < IW) ? src[gy*IW + gx] : 0.f;
        }
        if (tid < 9) sw[tid] = wt[ic*9 + tid];
        __syncthreads();
        #pragma unroll
        for (int ky = 0; ky < 3; ++ky)
            #pragma unroll
            for (int kx = 0; kx < 3; ++kx)
                acc = fmaf(sw[ky*3 + kx], sp[(yy + ky)*34 + xx + kx], acc);
        __syncthreads();
    }
    float v = acc + bias[0];
    v = alpha[0] * v;
    v = fminf(fmaxf(v, -20.f), 20.f);
    emet[b*HW + (y0 + yy)*IW + x0 + xx] = __expf(v);
}

// ======================= 3. softsplat ======================================
__global__ void zero_kernel(float* __restrict__ p, int n4)
{
    int idx = blockIdx.x * blockDim.x + threadIdx.x;
    if (idx < n4) reinterpret_cast<float4*>(p)[idx] = make_float4(0,0,0,0);
}

__global__ void splat_kernel(const float* __restrict__ feat,
                             const float* __restrict__ bi_flow,
                             int flow_ch,
                             const float* __restrict__ emet,  // [B,H,W]
                             float* __restrict__ num,         // [B,96,H,W]
                             float* __restrict__ den)         // [B,H,W]
{
    int idx = blockIdx.x * blockDim.x + threadIdx.x;
    if (idx >= NB*HW) return;
    int b = idx / HW;
    int p = idx - b*HW;
    int y = p / IW, x = p - y*IW;

    const float* fl = bi_flow + (b*4 + flow_ch)*HW;
    float tx = (float)x + fl[p]      * 0.125f;
    float ty = (float)y + fl[HW + p] * 0.125f;
    float x0f = floorf(tx), y0f = floorf(ty);
    float fx = tx - x0f, fy = ty - y0f;
    int x0 = (int)x0f, y0 = (int)y0f;
    int x1 = x0 + 1,  y1 = y0 + 1;
    bool vx0 = (x0 >= 0) & (x0 < IW), vx1 = (x1 >= 0) & (x1 < IW);
    bool vy0 = (y0 >= 0) & (y0 < IH), vy1 = (y1 >= 0) & (y1 < IH);
    bool v00 = vx0 & vy0, v10 = vx1 & vy0, v01 = vx0 & vy1, v11 = vx1 & vy1;
    float w00 = (1.f-fx)*(1.f-fy), w10 = fx*(1.f-fy);
    float w01 = (1.f-fx)*fy,       w11 = fx*fy;
    int t00 = y0*IW + x0, t10 = y0*IW + x1;
    int t01 = y1*IW + x0, t11 = y1*IW + x1;

    float m = emet[idx];

    const float* fb = feat + b*NC*HW + p;
    float* nb = num + b*NC*HW;
    for (int c = 0; c < NC; ++c) {
        float v = fb[c*HW] * m;
        float* chan = nb + c*HW;
        if (v00) atomicAdd(chan + t00, v*w00);
        if (v10) atomicAdd(chan + t10, v*w10);
        if (v01) atomicAdd(chan + t01, v*w01);
        if (v11) atomicAdd(chan + t11, v*w11);
    }
    float* db = den + b*HW;
    if (v00) atomicAdd(db + t00, m*w00);
    if (v10) atomicAdd(db + t10, m*w10);
    if (v01) atomicAdd(db + t01, m*w01);
    if (v11) atomicAdd(db + t11, m*w11);
}

// In-place: out = num/(den+eps), num aliases out.
__global__ void normalize_kernel(float* __restrict__ num,
                                 const float* __restrict__ den)
{
    int idx = blockIdx.x * blockDim.x + threadIdx.x;     // float4 index
    if (idx >= NB*NC*HW/4) return;
    int e = idx * 4;
    int b = e / (NC*HW);
    int p = e % HW;
    float4 n = reinterpret_cast<const float4*>(num)[idx];
    float4 d = *reinterpret_cast<const float4*>(den + b*HW + p);
    float4 o;
    o.x = n.x / (d.x + 1e-7f);
    o.y = n.y / (d.y + 1e-7f);
    o.z = n.z / (d.z + 1e-7f);
    o.w = n.w / (d.w + 1e-7f);
    reinterpret_cast<float4*>(num)[idx] = o;
}

// ======================= 4. correlation ====================================
__global__ __launch_bounds__(256, 1)
void corr_kernel(const float* __restrict__ wl,
                 const float* __restrict__ wr,
                 float* __restrict__ cost)
{
    __shared__ float sa[8*32];
    __shared__ float sb[16*40];
    int tid = threadIdx.x;
    int x0 = blockIdx.x * 32;
    int y0 = blockIdx.y * 8;
    int b  = blockIdx.z;
    int xx = tid & 31, yy = tid >> 5;   // 0..7

    float acc[81];
    #pragma unroll
    for (int d = 0; d < 81; ++d) acc[d] = 0.f;

    for (int c = 0; c < NC; ++c) {
        const float* lsrc = wl + (b*NC + c)*HW;
        const float* rsrc = wr + (b*NC + c)*HW;
        sa[tid] = lsrc[(y0 + yy)*IW + x0 + xx];
        for (int i = tid; i < 16*40; i += 256) {
            int r = i / 40, col = i - r*40;
            int gy = y0 - 4 + r, gx = x0 - 4 + col;
            sb[i] = (gy >= 0 && gy < IH && gx >= 0 && gx < IW) ? rsrc[gy*IW + gx] : 0.f;
        }
        __syncthreads();
        float a = sa[tid];
        #pragma unroll
        for (int dy = 0; dy < 9; ++dy)
            #pragma unroll
            for (int dx = 0; dx < 9; ++dx)
                acc[dy*9 + dx] = fmaf(a, sb[(yy + dy)*40 + xx + dx], acc[dy*9 + dx]);
        __syncthreads();
    }
    #pragma unroll
    for (int d = 0; d < 81; ++d) {
        float v = acc[d] * (1.f/96.f);
        v = v > 0.f ? v : 0.1f * v;
        cost[((b*81 + d)*IH + y0 + yy)*IW + x0 + xx] = v;
    }
}

// ======================= launch ============================================
extern "C" void kernel_launch(void* const* d_in, const int* in_sizes, int n_in,
                              void* d_out, int out_size)
{
    const float* bi_flow = (const float*)d_in[0];
    const float* fL      = (const float*)d_in[1];
    const float* fR      = (const float*)d_in[2];
    const float* alpha   = (const float*)d_in[3];
    const float* w1 = (const float*)d_in[4];
    const float* b1 = (const float*)d_in[5];
    const float* w2 = (const float*)d_in[6];
    const float* b2 = (const float*)d_in[7];
    const float* w3 = (const float*)d_in[8];
    const float* b3 = (const float*)d_in[9];

    float* out  = (float*)d_out;
    float* wL   = out;                       // 12,582,912 floats
    float* wR   = out + (size_t)NB*NC*HW;    // 12,582,912 floats
    float* cost = out + (size_t)2*NB*NC*HW;  // 10,616,832 floats

    // Scratch carved out of the cost region (dead before corr_kernel):
    float* s_mL    = cost;
    float* s_mR    = cost + 131072;
    float* s_emetL = cost + 262144;
    float* s_emetR = cost + 393216;
    float* s_denL  = cost + 524288;
    float* s_denR  = cost + 655360;
    float* s_x1 = wL;                        // conv1 out lives in wL region
    float* s_x2 = wR;                        // conv2 out lives in wR region

    const int SMEM_CONV = (2*A_BUF + 2*B_BUF) * sizeof(float);   // 55296 B
    cudaFuncSetAttribute(conv_mma_kernel<97, true>,
                         cudaFuncAttributeMaxDynamicSharedMemorySize, SMEM_CONV);
    cudaFuncSetAttribute(conv_mma_kernel<64, false>,
                         cudaFuncAttributeMaxDynamicSharedMemorySize, SMEM_CONV);

    const int NPIX = NB*HW;
    dim3 grid3(IW/32, IH/8, NB);             // conv3/corr: 256 threads
    const int CTILES = NB*512;               // 1024 conv tiles

    // ---- metrics ----
    warp_diff_kernel<<<(NPIX+255)/256, 256>>>(fL, fR, bi_flow, 0, s_mL);
    warp_diff_kernel<<<(NPIX+255)/256, 256>>>(fR, fL, bi_flow, 2, s_mR);

    // ---- metric_net L ----
    conv_mma_kernel<97, true><<<CTILES, 256, SMEM_CONV>>>(s_mL, fL, w1, b1, s_x1);
    conv_mma_kernel<64, false><<<CTILES, 256, SMEM_CONV>>>(nullptr, s_x1, w2, b2, s_x2);
    conv3_kernel<<<grid3, 256>>>(s_x2, w3, b3, alpha, s_emetL);

    // ---- metric_net R ----
    conv_mma_kernel<97, true><<<CTILES, 256, SMEM_CONV>>>(s_mR, fR, w1, b1, s_x1);
    conv_mma_kernel<64, false><<<CTILES, 256, SMEM_CONV>>>(nullptr, s_x1, w2, b2, s_x2);
    conv3_kernel<<<grid3, 256>>>(s_x2, w3, b3, alpha, s_emetR);

    // ---- softsplat L ----
    zero_kernel<<<(NB*NC*HW/4 + 255)/256, 256>>>(wL, NB*NC*HW/4);
    zero_kernel<<<(NPIX/4 + 255)/256, 256>>>(s_denL, NPIX/4);
    splat_kernel<<<(NPIX+255)/256, 256>>>(fL, bi_flow, 0, s_emetL, wL, s_denL);
    normalize_kernel<<<(NB*NC*HW/4 + 255)/256, 256>>>(wL, s_denL);

    // ---- softsplat R ----
    zero_kernel<<<(NB*NC*HW/4 + 255)/256, 256>>>(wR, NB*NC*HW/4);
    zero_kernel<<<(NPIX/4 + 255)/256, 256>>>(s_denR, NPIX/4);
    splat_kernel<<<(NPIX+255)/256, 256>>>(fR, bi_flow, 2, s_emetR, wR, s_denR);
    normalize_kernel<<<(NB*NC*HW/4 + 255)/256, 256>>>(wR, s_denR);

    // ---- correlation ----
    corr_kernel<<<grid3, 256>>>(wL, wR, cost);
}

// round 6
// speedup vs baseline: 1.5581x; 1.0254x over previous
#include <cuda_runtime.h>
#include <cuda.h>
#include <math.h>
#include <stdint.h>

#define IW 256
#define IH 256
#define HW (IW*IH)
#define NB 2
#define NC 96

// splat record: 48 channels + den + 3 pad = 52 floats (208 B, 16B-aligned)
#define REC 52
#define CHP 48               // channels per pass

__device__ __forceinline__ uint32_t f2tf32(float f){
    uint32_t r; asm("cvt.rna.tf32.f32 %0, %1;" : "=r"(r) : "f"(f)); return r;
}

// =============== tf32 mma.sync conv: NIC -> 64, 3x3 SAME, leaky 0.1 =========
#define AS_STRIDE 36
#define A_BUF (128*AS_STRIDE)
#define B_BUF (64*AS_STRIDE)

template<int NIC, bool HASM>
__global__ __launch_bounds__(256, 2)
void conv_mma_kernel(const float* __restrict__ metric,
                     const float* __restrict__ feat,
                     const float* __restrict__ wt,       // [64, NIC, 3, 3]
                     const float* __restrict__ bias,
                     float* __restrict__ out)            // [B,64,H,W]
{
    extern __shared__ float sm[];
    float* As = sm;                    // [2][A_BUF]
    float* Bs = sm + 2*A_BUF;          // [2][B_BUF]
    __shared__ float sbias[64];

    constexpr int KTOT = NIC*9;
    constexpr int NCH  = (KTOT + 31)/32;

    const int tid  = threadIdx.x;
    const int lane = tid & 31;
    const int warp = tid >> 5;
    const int wm = (warp >> 1) * 32;
    const int wn = (warp & 1) * 32;

    const int t  = blockIdx.x;
    const int b  = t >> 9;
    const int r  = t & 511;
    const int y0c = r >> 1;
    const int x0c = (r & 1) << 7;

    if (tid < 64) sbias[tid] = bias[tid];

    float acc[2][4][4];
    #pragma unroll
    for (int i = 0; i < 2; ++i)
        #pragma unroll
        for (int j = 0; j < 4; ++j)
            #pragma unroll
            for (int k = 0; k < 4; ++k) acc[i][j][k] = 0.f;

    float areg[16], breg[8];

    auto load_chunk = [&](int ch) {
        #pragma unroll
        for (int i = 0; i < 16; ++i) {
            int e    = tid + i*256;
            int m    = e >> 5;
            int kk32 = e & 31;
            int kk   = ch*32 + kk32;
            int ic   = kk / 9;
            int tap  = kk - ic*9;
            int ty   = tap / 3;
            int tx   = tap - ty*3;
            int x = x0c + m + tx - 1;
            int y = y0c + ty - 1;
            float v = 0.f;
            if (ic < NIC && (unsigned)x < IW && (unsigned)y < IH) {
                const float* src;
                if (HASM) src = (ic == 0) ? (metric + (size_t)b*HW)
                                          : (feat + ((size_t)b*(NIC-1) + (ic-1))*HW);
                else      src = feat + ((size_t)b*NIC + ic)*HW;
                v = __ldg(src + y*IW + x);
            }
            areg[i] = v;
        }
        #pragma unroll
        for (int i = 0; i < 8; ++i) {
            int e    = tid + i*256;
            int oc   = e >> 5;
            int kk32 = e & 31;
            int kk   = ch*32 + kk32;
            breg[i] = (kk < KTOT) ? __ldg(wt + (size_t)oc*KTOT + kk) : 0.f;
        }
    };
    auto store_chunk = [&](int buf) {
        float* ab = As + buf*A_BUF;
        float* bb = Bs + buf*B_BUF;
        #pragma unroll
        for (int i = 0; i < 16; ++i) {
            int e = tid + i*256;
            int m = e >> 5, kk32 = e & 31;
            ab[m*AS_STRIDE + kk32] = __uint_as_float(f2tf32(areg[i]));
        }
        #pragma unroll
        for (int i = 0; i < 8; ++i) {
            int e = tid + i*256;
            int oc = e >> 5, kk32 = e & 31;
            bb[oc*AS_STRIDE + kk32] = __uint_as_float(f2tf32(breg[i]));
        }
    };

    load_chunk(0);

    for (int s = 0; s < NCH; ++s) {
        const int buf = s & 1;
        store_chunk(buf);
        __syncthreads();
        if (s + 1 < NCH) load_chunk(s + 1);

        const float* ab = As + buf*A_BUF;
        const float* bb = Bs + buf*B_BUF;
        const int qr = lane >> 2;
        const int qc = lane & 3;

        #pragma unroll
        for (int k8 = 0; k8 < 4; ++k8) {
            const int k0 = k8*8;
            uint32_t afr[2][4];
            #pragma unroll
            for (int am = 0; am < 2; ++am) {
                const float* base = ab + (wm + am*16 + qr)*AS_STRIDE + k0 + qc;
                afr[am][0] = __float_as_uint(base[0]);
                afr[am][1] = __float_as_uint(base[8*AS_STRIDE]);
                afr[am][2] = __float_as_uint(base[4]);
                afr[am][3] = __float_as_uint(base[8*AS_STRIDE + 4]);
            }
            uint32_t bfr[4][2];
            #pragma unroll
            for (int j = 0; j < 4; ++j) {
                const float* base = bb + (wn + j*8 + qr)*AS_STRIDE + k0 + qc;
                bfr[j][0] = __float_as_uint(base[0]);
                bfr[j][1] = __float_as_uint(base[4]);
            }
            #pragma unroll
            for (int am = 0; am < 2; ++am)
                #pragma unroll
                for (int j = 0; j < 4; ++j)
                    asm volatile(
                        "mma.sync.aligned.m16n8k8.row.col.f32.tf32.tf32.f32 "
                        "{%0,%1,%2,%3}, {%4,%5,%6,%7}, {%8,%9}, {%0,%1,%2,%3};"
                        : "+f"(acc[am][j][0]), "+f"(acc[am][j][1]),
                          "+f"(acc[am][j][2]), "+f"(acc[am][j][3])
                        : "r"(afr[am][0]), "r"(afr[am][1]), "r"(afr[am][2]), "r"(afr[am][3]),
                          "r"(bfr[j][0]), "r"(bfr[j][1]));
        }
        __syncthreads();
    }

    const int qr = lane >> 2;
    const int qc = lane & 3;
    #pragma unroll
    for (int am = 0; am < 2; ++am) {
        #pragma unroll
        for (int j = 0; j < 4; ++j) {
            #pragma unroll
            for (int h = 0; h < 2; ++h) {
                int m  = wm + am*16 + qr + h*8;
                #pragma unroll
                for (int cc = 0; cc < 2; ++cc) {
                    int oc = wn + j*8 + qc*2 + cc;
                    float v = acc[am][j][h*2 + cc] + sbias[oc];
                    v = v > 0.f ? v : 0.1f * v;
                    out[(((size_t)b*64 + oc)*IH + y0c)*IW + x0c + m] = v;
                }
            }
        }
    }
}

// ======================= 1. backwarp + mean |diff| =========================
__global__ void warp_diff_kernel(const float* __restrict__ A,
                                 const float* __restrict__ Bf,
                                 const float* __restrict__ bi_flow,
                                 int flow_ch, float* __restrict__ mout)
{
    int idx = blockIdx.x * blockDim.x + threadIdx.x;
    if (idx >= NB*HW) return;
    int b = idx / HW;
    int p = idx - b*HW;
    int y = p / IW, x = p - y*IW;

    const float* fl = bi_flow + (b*4 + flow_ch) * HW;
    float tx = (float)x + fl[p]      * 0.125f;
    float ty = (float)y + fl[HW + p] * 0.125f;
    float x0f = floorf(tx), y0f = floorf(ty);
    float fx = tx - x0f, fy = ty - y0f;
    int x0 = (int)x0f, y0 = (int)y0f;
    int x1 = x0 + 1,  y1 = y0 + 1;

    bool vx0 = (x0 >= 0) & (x0 < IW), vx1 = (x1 >= 0) & (x1 < IW);
    bool vy0 = (y0 >= 0) & (y0 < IH), vy1 = (y1 >= 0) & (y1 < IH);
    bool v00 = vx0 & vy0, v10 = vx1 & vy0, v01 = vx0 & vy1, v11 = vx1 & vy1;
    float w00 = (1.f-fx)*(1.f-fy), w10 = fx*(1.f-fy);
    float w01 = (1.f-fx)*fy,       w11 = fx*fy;
    int o00 = v00 ? (y0*IW + x0) : 0;
    int o10 = v10 ? (y0*IW + x1) : 0;
    int o01 = v01 ? (y1*IW + x0) : 0;
    int o11 = v11 ? (y1*IW + x1) : 0;

    const float* Ab = A  + b*NC*HW + p;
    const float* Bb = Bf + b*NC*HW;
    float acc = 0.f;
    #pragma unroll 4
    for (int c = 0; c < NC; ++c) {
        const float* Bc = Bb + c*HW;
        float wv = 0.f;
        if (v00) wv += w00 * Bc[o00];
        if (v10) wv += w10 * Bc[o10];
        if (v01) wv += w01 * Bc[o01];
        if (v11) wv += w11 * Bc[o11];
        acc += fabsf(Ab[c*HW] - wv);
    }
    mout[idx] = acc * (1.f/96.f);
}

// conv3: 64 -> 1, then emet = exp(clip(alpha * (conv+b), -20, 20))
__global__ __launch_bounds__(256)
void conv3_kernel(const float* __restrict__ x,
                  const float* __restrict__ wt,   // [1,64,3,3]
                  const float* __restrict__ bias,
                  const float* __restrict__ alpha,
                  float* __restrict__ emet)       // [B,H,W]
{
    __shared__ float sp[10*34];
    __shared__ float sw[9];
    int tid = threadIdx.x;
    int x0 = blockIdx.x * 32;
    int y0 = blockIdx.y * 8;
    int b  = blockIdx.z;
    int xx = tid & 31, yy = tid >> 5;

    float acc = 0.f;
    for (int ic = 0; ic < 64; ++ic) {
        const float* src = x + (b*64 + ic)*HW;
        for (int i = tid; i < 10*34; i += 256) {
            int r = i / 34, c = i - r*34;
            int gy = y0 - 1 + r, gx = x0 - 1 + c;
            sp[i] = (gy >= 0 && gy < IH && gx >= 0 && gx < IW) ? src[gy*IW + gx] : 0.f;
        }
        if (tid < 9) sw[tid] = wt[ic*9 + tid];
        __syncthreads();
        #pragma unroll
        for (int ky = 0; ky < 3; ++ky)
            #pragma unroll
            for (int kx = 0; kx < 3; ++kx)
                acc = fmaf(sw[ky*3 + kx], sp[(yy + ky)*34 + xx + kx], acc);
        __syncthreads();
    }
    float v = acc + bias[0];
    v = alpha[0] * v;
    v = fminf(fmaxf(v, -20.f), 20.f);
    emet[b*HW + (y0 + yy)*IW + x0 + xx] = __expf(v);
}

// ======================= 3. softsplat (48-ch record passes) =================
// accum: [B*HW][REC] records; channels c0..c0+47 at [0..48), den at [48].
__global__ void splat48_kernel(const float* __restrict__ feat,
                               const float* __restrict__ bi_flow,
                               int flow_ch, int c0,
                               const float* __restrict__ emet,   // [B,H,W]
                               float* __restrict__ accum)
{
    int idx = blockIdx.x * blockDim.x + threadIdx.x;
    if (idx >= NB*HW) return;
    int b = idx / HW;
    int p = idx - b*HW;
    int y = p / IW, x = p - y*IW;

    const float* fl = bi_flow + (b*4 + flow_ch)*HW;
    float tx = (float)x + fl[p]      * 0.125f;
    float ty = (float)y + fl[HW + p] * 0.125f;
    float x0f = floorf(tx), y0f = floorf(ty);
    float fx = tx - x0f, fy = ty - y0f;
    int x0 = (int)x0f, y0 = (int)y0f;
    int x1 = x0 + 1,  y1 = y0 + 1;
    bool vx0 = (x0 >= 0) & (x0 < IW), vx1 = (x1 >= 0) & (x1 < IW);
    bool vy0 = (y0 >= 0) & (y0 < IH), vy1 = (y1 >= 0) & (y1 < IH);
    bool v00 = vx0 & vy0, v10 = vx1 & vy0, v01 = vx0 & vy1, v11 = vx1 & vy1;
    float w00 = (1.f-fx)*(1.f-fy), w10 = fx*(1.f-fy);
    float w01 = (1.f-fx)*fy,       w11 = fx*fy;
    int t00 = y0*IW + x0, t10 = y0*IW + x1;
    int t01 = y1*IW + x0, t11 = y1*IW + x1;

    float m = emet[idx];

    float vals[CHP];
    const float* fb = feat + ((size_t)b*NC + c0)*HW + p;
    #pragma unroll
    for (int c = 0; c < CHP; ++c) vals[c] = fb[(size_t)c*HW] * m;

    float* ab = accum + (size_t)b*HW*REC;

    #define DO_CORNER(valid, tgt, w) do {                                     \
        if (valid) {                                                          \
            float* base = ab + (size_t)(tgt)*REC;                             \
            float wv = (w);                                                   \
            _Pragma("unroll")                                                 \
            for (int k = 0; k < CHP/4; ++k) {                                 \
                asm volatile("red.global.add.v4.f32 [%0], {%1,%2,%3,%4};"     \
                    :: "l"(base + 4*k),                                       \
                       "f"(vals[4*k+0]*wv), "f"(vals[4*k+1]*wv),              \
                       "f"(vals[4*k+2]*wv), "f"(vals[4*k+3]*wv)               \
                    : "memory");                                              \
            }                                                                 \
            atomicAdd(base + CHP, m*wv);                                      \
        }                                                                     \
    } while(0)

    DO_CORNER(v00, t00, w00);
    DO_CORNER(v10, t10, w10);
    DO_CORNER(v01, t01, w01);
    DO_CORNER(v11, t11, w11);
    #undef DO_CORNER
}

// Transposing normalize: records -> out[B, c0..c0+47, H, W]
__global__ __launch_bounds__(256)
void normalize48_kernel(const float* __restrict__ accum,
                        int c0,
                        float* __restrict__ out)   // [B,96,H,W] base
{
    __shared__ float s[32*53];
    const int tid = threadIdx.x;
    const int pbase = blockIdx.x * 32;          // global pixel idx (b*HW + p)
    const int b = pbase / HW;
    const int prow = pbase - b*HW;

    const float4* a4 = reinterpret_cast<const float4*>(accum);
    #pragma unroll
    for (int it = 0; it < 2; ++it) {
        int i = tid + it*256;
        if (i < 32*13) {
            int px = i / 13, k = i - px*13;
            float4 v = a4[(size_t)(pbase + px)*13 + k];
            float* d = s + px*53 + 4*k;
            d[0] = v.x; d[1] = v.y; d[2] = v.z; d[3] = v.w;
        }
    }
    __syncthreads();

    #pragma unroll
    for (int it = 0; it < 6; ++it) {
        int i = tid + it*256;               // 1536 total
        int c  = i >> 5;
        int px = i & 31;
        float num = s[px*53 + c];
        float den = s[px*53 + CHP];
        out[((size_t)b*NC + c0 + c)*HW + prow + px] = num / (den + 1e-7f);
    }
}

// ======================= 4. correlation ====================================
__global__ __launch_bounds__(256, 1)
void corr_kernel(const float* __restrict__ wl,
                 const float* __restrict__ wr,
                 float* __restrict__ cost)
{
    __shared__ float sa[8*32];
    __shared__ float sb[16*40];
    int tid = threadIdx.x;
    int x0 = blockIdx.x * 32;
    int y0 = blockIdx.y * 8;
    int b  = blockIdx.z;
    int xx = tid & 31, yy = tid >> 5;

    float acc[81];
    #pragma unroll
    for (int d = 0; d < 81; ++d) acc[d] = 0.f;

    for (int c = 0; c < NC; ++c) {
        const float* lsrc = wl + (b*NC + c)*HW;
        const float* rsrc = wr + (b*NC + c)*HW;
        sa[tid] = lsrc[(y0 + yy)*IW + x0 + xx];
        for (int i = tid; i < 16*40; i += 256) {
            int r = i / 40, col = i - r*40;
            int gy = y0 - 4 + r, gx = x0 - 4 + col;
            sb[i] = (gy >= 0 && gy < IH && gx >= 0 && gx < IW) ? rsrc[gy*IW + gx] : 0.f;
        }
        __syncthreads();
        float a = sa[tid];
        #pragma unroll
        for (int dy = 0; dy < 9; ++dy)
            #pragma unroll
            for (int dx = 0; dx < 9; ++dx)
                acc[dy*9 + dx] = fmaf(a, sb[(yy + dy)*40 + xx + dx], acc[dy*9 + dx]);
        __syncthreads();
    }
    #pragma unroll
    for (int d = 0; d < 81; ++d) {
        float v = acc[d] * (1.f/96.f);
        v = v > 0.f ? v : 0.1f * v;
        cost[((b*81 + d)*IH + y0 + yy)*IW + x0 + xx] = v;
    }
}

// ======================= launch ============================================
extern "C" void kernel_launch(void* const* d_in, const int* in_sizes, int n_in,
                              void* d_out, int out_size)
{
    const float* bi_flow = (const float*)d_in[0];
    const float* fL      = (const float*)d_in[1];
    const float* fR      = (const float*)d_in[2];
    const float* alpha   = (const float*)d_in[3];
    const float* w1 = (const float*)d_in[4];
    const float* b1 = (const float*)d_in[5];
    const float* w2 = (const float*)d_in[6];
    const float* b2 = (const float*)d_in[7];
    const float* w3 = (const float*)d_in[8];
    const float* b3 = (const float*)d_in[9];

    float* out  = (float*)d_out;
    float* wL   = out;                       // 12,582,912 floats
    float* wR   = out + (size_t)NB*NC*HW;    // 12,582,912 floats
    float* cost = out + (size_t)2*NB*NC*HW;  // 10,616,832 floats

    // accum records at head of cost region: NB*HW*REC = 6,815,744 floats
    float* s_accum = cost;
    // small scraps at the tail of cost region (dead before corr):
    float* s_tail  = cost + 10616832 - 4*131072;   // 10,092,544
    float* s_mL    = s_tail;
    float* s_mR    = s_tail + 131072;
    float* s_emetL = s_tail + 262144;
    float* s_emetR = s_tail + 393216;
    float* s_x1 = wL;                        // conv scratch (dead before splats)
    float* s_x2 = wR;

    const int SMEM_CONV = (2*A_BUF + 2*B_BUF) * sizeof(float);   // 55296 B
    cudaFuncSetAttribute(conv_mma_kernel<97, true>,
                         cudaFuncAttributeMaxDynamicSharedMemorySize, SMEM_CONV);
    cudaFuncSetAttribute(conv_mma_kernel<64, false>,
                         cudaFuncAttributeMaxDynamicSharedMemorySize, SMEM_CONV);

    const int NPIX = NB*HW;
    const size_t ACCUM_BYTES = (size_t)NB*HW*REC*sizeof(float);
    dim3 grid3(IW/32, IH/8, NB);
    const int CTILES = NB*512;
    const int NORMB = NPIX/32;

    // ---- metrics ----
    warp_diff_kernel<<<(NPIX+255)/256, 256>>>(fL, fR, bi_flow, 0, s_mL);
    warp_diff_kernel<<<(NPIX+255)/256, 256>>>(fR, fL, bi_flow, 2, s_mR);

    // ---- metric_net L ----
    conv_mma_kernel<97, true><<<CTILES, 256, SMEM_CONV>>>(s_mL, fL, w1, b1, s_x1);
    conv_mma_kernel<64, false><<<CTILES, 256, SMEM_CONV>>>(nullptr, s_x1, w2, b2, s_x2);
    conv3_kernel<<<grid3, 256>>>(s_x2, w3, b3, alpha, s_emetL);

    // ---- metric_net R ----
    conv_mma_kernel<97, true><<<CTILES, 256, SMEM_CONV>>>(s_mR, fR, w1, b1, s_x1);
    conv_mma_kernel<64, false><<<CTILES, 256, SMEM_CONV>>>(nullptr, s_x1, w2, b2, s_x2);
    conv3_kernel<<<grid3, 256>>>(s_x2, w3, b3, alpha, s_emetR);

    // ---- softsplat L (two 48-channel passes) ----
    for (int c0 = 0; c0 < NC; c0 += CHP) {
        cudaMemsetAsync(s_accum, 0, ACCUM_BYTES);
        splat48_kernel<<<(NPIX+255)/256, 256>>>(fL, bi_flow, 0, c0, s_emetL, s_accum);
        normalize48_kernel<<<NORMB, 256>>>(s_accum, c0, wL);
    }

    // ---- softsplat R ----
    for (int c0 = 0; c0 < NC; c0 += CHP) {
        cudaMemsetAsync(s_accum, 0, ACCUM_BYTES);
        splat48_kernel<<<(NPIX+255)/256, 256>>>(fR, bi_flow, 2, c0, s_emetR, s_accum);
        normalize48_kernel<<<NORMB, 256>>>(s_accum, c0, wR);
    }

    // ---- correlation (overwrites all cost-region scratch) ----
    corr_kernel<<<grid3, 256>>>(wL, wR, cost);
}